// round 15
// baseline (speedup 1.0000x reference)
#include <cuda_runtime.h>
#include <cuda_bf16.h>
#include <cstdint>

#define NTOK 1024
#define CDIM 768
#define NH   12
#define HD   64
#define NB   8
#define BHN  (NB*NH)               /* 96  */
#define KV_ELEMS (BHN*NTOK*HD)     /* 6291456 */
#define OUT_ELEMS (NB*NTOK*CDIM)   /* 6291456 */

__device__ float g_REL[KV_ELEMS];   // per (bh,n): [0,32)=rel_h, [32,64)=rel_w (×log2e)

// bf16 hi/lo split buffers
__device__ __nv_bfloat16 g_Xhi[OUT_ELEMS],  g_Xlo[OUT_ELEMS];
__device__ __nv_bfloat16 g_Wqhi[3*CDIM*CDIM], g_Wqlo[3*CDIM*CDIM];
__device__ __nv_bfloat16 g_Wphi[CDIM*CDIM], g_Wplo[CDIM*CDIM];
__device__ __nv_bfloat16 g_AOhi[OUT_ELEMS], g_AOlo[OUT_ELEMS];
__device__ __nv_bfloat16 g_Qhi[KV_ELEMS], g_Qlo[KV_ELEMS];   // scaled by 0.125*log2e
__device__ __nv_bfloat16 g_Khi[KV_ELEMS], g_Klo[KV_ELEMS];
__device__ __nv_bfloat16 g_Vhi[KV_ELEMS], g_Vlo[KV_ELEMS];

// single dynamic smem symbol shared by all kernels
extern __shared__ __align__(16) char dyn_sm[];

// ---------------------------------------------------------------------------
__device__ __forceinline__ uint32_t smem_u32(const void* p) {
    uint32_t a;
    asm("{ .reg .u64 t; cvta.to.shared.u64 t, %1; cvt.u32.u64 %0, t; }" : "=r"(a) : "l"(p));
    return a;
}
__device__ __forceinline__ void ldm_x4(uint32_t* r, uint32_t addr) {
    asm volatile("ldmatrix.sync.aligned.m8n8.x4.shared.b16 {%0,%1,%2,%3}, [%4];"
                 : "=r"(r[0]), "=r"(r[1]), "=r"(r[2]), "=r"(r[3]) : "r"(addr));
}
__device__ __forceinline__ void ldm_x4t(uint32_t* r, uint32_t addr) {
    asm volatile("ldmatrix.sync.aligned.m8n8.x4.trans.shared.b16 {%0,%1,%2,%3}, [%4];"
                 : "=r"(r[0]), "=r"(r[1]), "=r"(r[2]), "=r"(r[3]) : "r"(addr));
}
__device__ __forceinline__ void mma16816(float* d, const uint32_t* a, const uint32_t* b) {
    asm volatile(
        "mma.sync.aligned.m16n8k16.row.col.f32.bf16.bf16.f32 "
        "{%0,%1,%2,%3}, {%4,%5,%6,%7}, {%8,%9}, {%0,%1,%2,%3};"
        : "+f"(d[0]), "+f"(d[1]), "+f"(d[2]), "+f"(d[3])
        : "r"(a[0]), "r"(a[1]), "r"(a[2]), "r"(a[3]), "r"(b[0]), "r"(b[1]));
}
__device__ __forceinline__ void sts128(uint32_t addr, uint4 v) {
    asm volatile("st.shared.v4.b32 [%0], {%1, %2, %3, %4};"
                 :: "r"(addr), "r"(v.x), "r"(v.y), "r"(v.z), "r"(v.w) : "memory");
}
__device__ __forceinline__ void cp16(uint32_t dst, const void* src) {
    asm volatile("cp.async.cg.shared.global [%0], [%1], 16;" :: "r"(dst), "l"(src));
}
#define CP_COMMIT asm volatile("cp.async.commit_group;" ::: "memory")
#define CP_WAIT0  asm volatile("cp.async.wait_group 0;" ::: "memory")

// 32B-row swizzle (gemm tiles)
__device__ __forceinline__ uint32_t tswz(int r, int c) {
    return (uint32_t)(r * 32 + 16 * (c ^ ((r >> 2) & 1)));
}
// 128B-row swizzle (attention tiles)
__device__ __forceinline__ uint32_t a128(int r, int c) {
    return (uint32_t)(r * 128 + 16 * (c ^ (r & 7)));
}
// pack (lo, hi) floats -> bf16x2
__device__ __forceinline__ uint32_t pack_bf16(float lo, float hi) {
    uint32_t r;
    asm("cvt.rn.bf16x2.f32 %0, %1, %2;" : "=r"(r) : "f"(hi), "f"(lo));
    return r;
}
__device__ __forceinline__ float lo_f(uint32_t h) { return __uint_as_float(h << 16); }
__device__ __forceinline__ float hi_f(uint32_t h) { return __uint_as_float(h & 0xFFFF0000u); }

// fast exp2 on the FMA pipe: input already in log2 domain.
__device__ __forceinline__ float fexp2(float y) {
    float r = y + 12582912.f;
    float n = r - 12582912.f;
    float f = y - n;
    uint32_t i = __float_as_uint(r);
    float s = __uint_as_float((i + (uint32_t)(127 - 0x4B400000)) << 23);
    float p = 0.00961812911f;
    p = fmaf(p, f, 0.0555041087f);
    p = fmaf(p, f, 0.240226507f);
    p = fmaf(p, f, 0.69314718056f);
    p = fmaf(p, f, 1.0f);
    return s * p;
}

// ---------------------------------------------------------------------------
// Fused conversion: one launch converts X, qkv_w, proj_w to bf16 hi/lo.
// ---------------------------------------------------------------------------
#define CVT_NB1 (OUT_ELEMS / 1024)
#define CVT_NB2 ((3 * CDIM * CDIM) / 1024)
#define CVT_NB3 ((CDIM * CDIM) / 1024)

__global__ void __launch_bounds__(256) cvt_all(
        const float* __restrict__ x, const float* __restrict__ qw,
        const float* __restrict__ pw)
{
    const float* src;
    __nv_bfloat16 *hi, *lo;
    int base;
    if (blockIdx.x < CVT_NB1) {
        src = x; hi = g_Xhi; lo = g_Xlo; base = blockIdx.x;
    } else if (blockIdx.x < CVT_NB1 + CVT_NB2) {
        src = qw; hi = g_Wqhi; lo = g_Wqlo; base = blockIdx.x - CVT_NB1;
    } else {
        src = pw; hi = g_Wphi; lo = g_Wplo; base = blockIdx.x - CVT_NB1 - CVT_NB2;
    }
    int i = (base * 256 + threadIdx.x) * 4;
    float4 v = *(const float4*)(src + i);
    uint32_t h0 = pack_bf16(v.x, v.y), h1 = pack_bf16(v.z, v.w);
    uint32_t l0 = pack_bf16(v.x - lo_f(h0), v.y - hi_f(h0));
    uint32_t l1 = pack_bf16(v.z - lo_f(h1), v.w - hi_f(h1));
    ((uint32_t*)(hi + i))[0] = h0; ((uint32_t*)(hi + i))[1] = h1;
    ((uint32_t*)(lo + i))[0] = l0; ((uint32_t*)(lo + i))[1] = l1;
}

// ---------------------------------------------------------------------------
// HMMA bf16x3 GEMM with cp.async 2-stage pipeline (proven config).
// ---------------------------------------------------------------------------
#define STG 16384

__global__ void __launch_bounds__(256, 2) gemm_mma(
        const __nv_bfloat16* __restrict__ Ahi, const __nv_bfloat16* __restrict__ Alo,
        const __nv_bfloat16* __restrict__ Bhi, const __nv_bfloat16* __restrict__ Blo,
        const float* __restrict__ bias, float* __restrict__ out0,
        float* __restrict__ out1, int mode)
{
    __shared__ __align__(16) char smem[2 * STG];
    const uint32_t sb = smem_u32(smem);
    const int tid = threadIdx.x, wid = tid >> 5, lane = tid & 31;
    const int m0 = blockIdx.y * 128, n0 = blockIdx.x * 128;
    const int wm = wid & 1, wn = wid >> 1;

    const int lr = tid >> 1, lc = tid & 1;
    const uint32_t soff = tswz(lr, lc);
    const __nv_bfloat16* gAh = Ahi + (size_t)(m0 + lr) * CDIM + lc * 8;
    const __nv_bfloat16* gAl = Alo + (size_t)(m0 + lr) * CDIM + lc * 8;
    const __nv_bfloat16* gBh = Bhi + (size_t)(n0 + lr) * CDIM + lc * 8;
    const __nv_bfloat16* gBl = Blo + (size_t)(n0 + lr) * CDIM + lc * 8;

    uint32_t aoff[4], boff[2];
#pragma unroll
    for (int mf = 0; mf < 4; mf++) {
        int r = wm * 64 + mf * 16 + (lane & 7) + ((lane >> 3) & 1) * 8;
        aoff[mf] = tswz(r, lane >> 4);
    }
#pragma unroll
    for (int g = 0; g < 2; g++) {
        int r = wn * 32 + g * 16 + ((lane >> 4) & 1) * 8 + (lane & 7);
        boff[g] = tswz(r, (lane >> 3) & 1);
    }

    float acc[4][4][4];
#pragma unroll
    for (int i = 0; i < 4; i++)
#pragma unroll
        for (int j = 0; j < 4; j++)
#pragma unroll
            for (int v = 0; v < 4; v++) acc[i][j][v] = 0.f;

    cp16(sb + soff, gAh);
    cp16(sb + 4096 + soff, gAl);
    cp16(sb + 8192 + soff, gBh);
    cp16(sb + 12288 + soff, gBl);
    CP_COMMIT; CP_WAIT0;
    __syncthreads();

#pragma unroll 2
    for (int kt = 0; kt < 48; kt++) {
        const uint32_t cur = sb + (kt & 1) * STG;
        if (kt < 47) {
            const uint32_t nxt = sb + ((kt + 1) & 1) * STG;
            const int ko = (kt + 1) * 16;
            cp16(nxt + soff, gAh + ko);
            cp16(nxt + 4096 + soff, gAl + ko);
            cp16(nxt + 8192 + soff, gBh + ko);
            cp16(nxt + 12288 + soff, gBl + ko);
            CP_COMMIT;
        }

        uint32_t bh[8], bl[8];
        ldm_x4(bh,     cur + 8192  + boff[0]);
        ldm_x4(bh + 4, cur + 8192  + boff[1]);
        ldm_x4(bl,     cur + 12288 + boff[0]);
        ldm_x4(bl + 4, cur + 12288 + boff[1]);

#pragma unroll
        for (int mf = 0; mf < 4; mf++) {
            uint32_t ah[4], al[4];
            ldm_x4(ah, cur + aoff[mf]);
            ldm_x4(al, cur + 4096 + aoff[mf]);
#pragma unroll
            for (int nf = 0; nf < 4; nf++) {
                const uint32_t* ph = &bh[(nf >> 1) * 4 + (nf & 1) * 2];
                const uint32_t* pl = &bl[(nf >> 1) * 4 + (nf & 1) * 2];
                mma16816(acc[mf][nf], ah, ph);
                mma16816(acc[mf][nf], ah, pl);
                mma16816(acc[mf][nf], al, ph);
            }
        }
        CP_WAIT0;
        __syncthreads();
    }

#pragma unroll
    for (int mf = 0; mf < 4; mf++) {
#pragma unroll
        for (int nf = 0; nf < 4; nf++) {
            const int col = n0 + wn * 32 + nf * 8 + (lane & 3) * 2;
            const int r1 = m0 + wm * 64 + mf * 16 + (lane >> 2);
            const float2 bb = *(const float2*)(bias + col);
            float2 v0 = make_float2(acc[mf][nf][0] + bb.x, acc[mf][nf][1] + bb.y);
            float2 v1 = make_float2(acc[mf][nf][2] + bb.x, acc[mf][nf][3] + bb.y);
            if (mode == 0) {
                *(float2*)(out0 + (size_t)r1 * CDIM + col) = v0;
                *(float2*)(out0 + (size_t)(r1 + 8) * CDIM + col) = v1;
            } else {
                const int t = col / CDIM, rem = col - t * CDIM;
                const int h = rem >> 6, d = rem & 63;
                float* dst = (t == 1) ? out1 : out1 + KV_ELEMS;
                __nv_bfloat16* hib = (t == 0) ? g_Qhi : (t == 1) ? g_Khi : g_Vhi;
                __nv_bfloat16* lob = (t == 0) ? g_Qlo : (t == 1) ? g_Klo : g_Vlo;
                // Q scale = 0.125 * log2(e): scores and rel bias land in log2 domain
                const float sc = (t == 0) ? 0.18033688011112042f : 1.f;
#pragma unroll
                for (int rr = 0; rr < 2; rr++) {
                    const int row = r1 + rr * 8;
                    const int b = row >> 10, n = row & (NTOK - 1);
                    const size_t idx = ((size_t)(b * NH + h) << 16) | ((size_t)n << 6) | (size_t)d;
                    float2 vv = rr ? v1 : v0;
                    if (t != 0) *(float2*)(dst + idx) = vv;
                    float sx = vv.x * sc, sy = vv.y * sc;
                    uint32_t hh = pack_bf16(sx, sy);
                    uint32_t ll = pack_bf16(sx - lo_f(hh), sy - hi_f(hh));
                    *(uint32_t*)(hib + idx) = hh;
                    *(uint32_t*)(lob + idx) = ll;
                }
            }
        }
    }
}

// ---------------------------------------------------------------------------
// rel-pos projections via HMMA (bf16x3). (R10 proven config.)
// ---------------------------------------------------------------------------
#define RSM_TOT 49152

__global__ void __launch_bounds__(128) rel_mma(
        const float* __restrict__ rph, const float* __restrict__ rpw)
{
    const uint32_t sb = smem_u32(dyn_sm);
    const uint32_t Qh = sb, Ql = sb + 16384;
    const uint32_t Th = sb + 32768, Tl = sb + 40960;

    const int bh = blockIdx.x;
    const int grp = blockIdx.y;
    const bool isw = grp >= 8;
    const int g = grp & 7;
    const int tid = threadIdx.x, wid = tid >> 5, lane = tid & 31;

    {
        const int s = tid;
        const int q = isw ? (g * 4 + (s >> 5) + 32 * (s & 31))
                          : (g * 128 + s);
        const size_t gb = ((size_t)bh << 16) | ((size_t)q << 6);
        const uint4* qh = (const uint4*)(g_Qhi + gb);
        const uint4* ql = (const uint4*)(g_Qlo + gb);
#pragma unroll
        for (int c = 0; c < 8; c++) {
            sts128(Qh + a128(s, c), qh[c]);
            sts128(Ql + a128(s, c), ql[c]);
        }
    }
    {
        const float* tab = isw ? rpw : rph;
        for (int i = tid; i < 63 * 32; i += 128) {
            const int r = i >> 5, c2 = (i & 31) * 2;
            float2 v = *(const float2*)(tab + r * 64 + c2);
            uint32_t h = pack_bf16(v.x, v.y);
            uint32_t l = pack_bf16(v.x - lo_f(h), v.y - hi_f(h));
            const int boffb = c2 * 2;
            const uint32_t a = a128(r, boffb >> 4) + (boffb & 15);
            *(uint32_t*)(dyn_sm + (Th - sb) + a) = h;
            *(uint32_t*)(dyn_sm + (Tl - sb) + a) = l;
        }
    }
    __syncthreads();

    const int vv = g * 4 + wid;
    const int abase = wid * 32;

    float acc[2][4][4];
#pragma unroll
    for (int mf = 0; mf < 2; mf++)
#pragma unroll
        for (int nf = 0; nf < 4; nf++)
#pragma unroll
            for (int v = 0; v < 4; v++) acc[mf][nf][v] = 0.f;

    const int arow_l = (lane & 7) + ((lane >> 3) & 1) * 8;
    const int nloc  = ((lane >> 4) & 1) * 8 + (lane & 7);
    const int bchunk = (lane >> 3) & 1;

#pragma unroll
    for (int ks = 0; ks < 4; ks++) {
        uint32_t ah[2][4], al[2][4];
#pragma unroll
        for (int mf = 0; mf < 2; mf++) {
            const uint32_t aaddr = Qh + a128(abase + mf * 16 + arow_l, 2 * ks + (lane >> 4));
            ldm_x4(ah[mf], aaddr);
            ldm_x4(al[mf], aaddr + 16384);
        }
#pragma unroll
        for (int g2 = 0; g2 < 2; g2++) {
            const int trow = vv + 31 - (g2 * 16 + nloc);
            uint32_t bhf[4], blf[4];
            const uint32_t baddr = a128(trow, 2 * ks + bchunk);
            ldm_x4(bhf, Th + baddr);
            ldm_x4(blf, Tl + baddr);
#pragma unroll
            for (int mf = 0; mf < 2; mf++) {
#pragma unroll
                for (int half = 0; half < 2; half++) {
                    float* d = acc[mf][g2 * 2 + half];
                    mma16816(d, ah[mf], bhf + half * 2);
                    mma16816(d, ah[mf], blf + half * 2);
                    mma16816(d, al[mf], bhf + half * 2);
                }
            }
        }
    }

    const int cbase = isw ? 32 : 0;
#pragma unroll
    for (int mf = 0; mf < 2; mf++)
#pragma unroll
        for (int nf = 0; nf < 4; nf++) {
            const int col = cbase + nf * 8 + (lane & 3) * 2;
#pragma unroll
            for (int rr = 0; rr < 2; rr++) {
                const int rl = mf * 16 + (lane >> 2) + rr * 8;
                const int q = isw ? (vv + 32 * rl) : (g * 128 + abase + rl);
                float2 o = make_float2(acc[mf][nf][rr * 2] * 8.f,
                                       acc[mf][nf][rr * 2 + 1] * 8.f);
                *(float2*)(g_REL + (((size_t)bh << 16) | ((size_t)q << 6)) + col) = o;
            }
        }
}

// ---------------------------------------------------------------------------
// Tensor-core flash attention: 4 warps x 32 q-rows, bf16x3, base-2 fixed-
// shift softmax, cp.async double-buffered K/V. t-loop unrolled x2 so each
// body has a compile-time stage base (address ALU hoisted).
// ---------------------------------------------------------------------------
#define ASM_TOT 114688
#define KVB 49152

__global__ void __launch_bounds__(128, 2) attn_mma()
{
    const uint32_t sb = smem_u32(dyn_sm);
    const uint32_t Qh = sb, Ql = sb + 16384;
    float* RELh = (float*)(dyn_sm + 32768);

    const int bh = blockIdx.y, q0 = blockIdx.x * 128;
    const int tid = threadIdx.x, wid = tid >> 5, lane = tid & 31;

    const int arr = wid, kr0 = lane;
    const __nv_bfloat16* kvsrc = (arr == 0) ? g_Khi : (arr == 1) ? g_Klo
                               : (arr == 2) ? g_Vhi : g_Vlo;
    kvsrc += ((size_t)bh << 16) | ((size_t)kr0 << 6);

    {
        const uint32_t dst = sb + KVB + arr * 8192;
#pragma unroll
        for (int c = 0; c < 8; c++) {
            cp16(dst + a128(kr0, c), kvsrc + c * 8);
            cp16(dst + a128(kr0 + 32, c), kvsrc + 32 * 64 + c * 8);
        }
        CP_COMMIT;
    }

    {
        const int row = tid;
        const size_t gb = ((size_t)bh << 16) | ((size_t)(q0 + row) << 6);
        const uint4* qh = (const uint4*)(g_Qhi + gb);
        const uint4* ql = (const uint4*)(g_Qlo + gb);
#pragma unroll
        for (int c = 0; c < 8; c++) {
            sts128(Qh + a128(row, c), qh[c]);
            sts128(Ql + a128(row, c), ql[c]);
        }
        const float4* rs = (const float4*)(g_REL + gb);
        float4* rd = (float4*)(RELh + row * 32);
#pragma unroll
        for (int c = 0; c < 8; c++) rd[c] = rs[c];
    }

    const int qr = wid * 32;

    float rw[4][8];
#pragma unroll
    for (int mf = 0; mf < 2; mf++)
#pragma unroll
        for (int rr = 0; rr < 2; rr++) {
            const int row = q0 + qr + mf * 16 + (lane >> 2) + rr * 8;
            const float* src = g_REL + (((size_t)bh << 16) | ((size_t)row << 6)) + 32;
#pragma unroll
            for (int c = 0; c < 2; c++)
#pragma unroll
                for (int f4 = 0; f4 < 4; f4++)
                    rw[mf * 2 + rr][c + 2 * f4] = src[(lane & 3) * 2 + c + f4 * 8];
        }

    float O[2][8][4];
#pragma unroll
    for (int mf = 0; mf < 2; mf++)
#pragma unroll
        for (int f = 0; f < 8; f++)
#pragma unroll
            for (int v = 0; v < 4; v++) O[mf][f][v] = 0.f;
    float l_[2][2] = {{0.f, 0.f}, {0.f, 0.f}};

    CP_WAIT0;
    __syncthreads();

#pragma unroll 2
    for (int t = 0; t < 16; t++) {
        const uint32_t kvb = sb + KVB + (t & 1) * 32768;
        if (t < 15) {
            const uint32_t dst = sb + KVB + ((t + 1) & 1) * 32768 + arr * 8192;
            const __nv_bfloat16* src = kvsrc + ((size_t)(t + 1) << 12);
#pragma unroll
            for (int c = 0; c < 8; c++) {
                cp16(dst + a128(kr0, c), src + c * 8);
                cp16(dst + a128(kr0 + 32, c), src + 32 * 64 + c * 8);
            }
            CP_COMMIT;
        }
        const uint32_t Kh = kvb, Vh = kvb + 16384;

        float S[2][8][4];
#pragma unroll
        for (int mf = 0; mf < 2; mf++)
#pragma unroll
            for (int f = 0; f < 8; f++)
#pragma unroll
                for (int v = 0; v < 4; v++) S[mf][f][v] = 0.f;

#pragma unroll
        for (int ks = 0; ks < 4; ks++) {
            uint32_t ah[2][4], al[2][4];
#pragma unroll
            for (int mf = 0; mf < 2; mf++) {
                const uint32_t aaddr = Qh + a128(qr + mf * 16 + (lane & 7) + ((lane >> 3) & 1) * 8,
                                                 2 * ks + (lane >> 4));
                ldm_x4(ah[mf], aaddr);
                ldm_x4(al[mf], aaddr + 16384);
            }
#pragma unroll
            for (int g = 0; g < 4; g++) {
                uint32_t kb[4], kl[4];
                const uint32_t kaddr = Kh + a128(g * 16 + ((lane >> 4) & 1) * 8 + (lane & 7),
                                                 2 * ks + ((lane >> 3) & 1));
                ldm_x4(kb, kaddr);
                ldm_x4(kl, kaddr + 8192);
#pragma unroll
                for (int mf = 0; mf < 2; mf++) {
                    mma16816(S[mf][2*g],   ah[mf], kb);     mma16816(S[mf][2*g],   ah[mf], kl);
                    mma16816(S[mf][2*g],   al[mf], kb);
                    mma16816(S[mf][2*g+1], ah[mf], kb + 2); mma16816(S[mf][2*g+1], ah[mf], kl + 2);
                    mma16816(S[mf][2*g+1], al[mf], kb + 2);
                }
            }
        }

        const int khb = t * 2;
#pragma unroll
        for (int mf = 0; mf < 2; mf++)
#pragma unroll
            for (int rr = 0; rr < 2; rr++) {
                const int row = qr + mf * 16 + (lane >> 2) + rr * 8;
                const float rh0 = RELh[row * 32 + khb], rh1 = RELh[row * 32 + khb + 1];
                float ps0 = 0.f, ps1 = 0.f;
#pragma unroll
                for (int f = 0; f < 8; f++) {
                    const float rh = (f < 4) ? rh0 : rh1;
                    float p0 = fexp2(S[mf][f][rr*2]   + rh + rw[mf*2+rr][0 + 2*(f & 3)]);
                    float p1 = fexp2(S[mf][f][rr*2+1] + rh + rw[mf*2+rr][1 + 2*(f & 3)]);
                    S[mf][f][rr*2] = p0; S[mf][f][rr*2+1] = p1;
                    ps0 += p0; ps1 += p1;
                }
                l_[mf][rr] += ps0 + ps1;
            }

        // P repack (hi/lo) + PV MMAs (full bf16x3)
#pragma unroll
        for (int ks = 0; ks < 4; ks++) {
            uint32_t ph[2][4], pl[2][4];
#pragma unroll
            for (int mf = 0; mf < 2; mf++)
#pragma unroll
                for (int part = 0; part < 4; part++) {
                    const int f = 2 * ks + (part >> 1);
                    const float x0 = S[mf][f][(part & 1) * 2], x1 = S[mf][f][(part & 1) * 2 + 1];
                    uint32_t h = pack_bf16(x0, x1);
                    ph[mf][part] = h;
                    pl[mf][part] = pack_bf16(x0 - lo_f(h), x1 - hi_f(h));
                }
#pragma unroll
            for (int dg = 0; dg < 4; dg++) {
                uint32_t vb[4], vl[4];
                const uint32_t vaddr = Vh + a128(ks * 16 + ((lane >> 3) & 1) * 8 + (lane & 7),
                                                 2 * dg + (lane >> 4));
                ldm_x4t(vb, vaddr);
                ldm_x4t(vl, vaddr + 8192);
#pragma unroll
                for (int mf = 0; mf < 2; mf++) {
                    mma16816(O[mf][2*dg],   ph[mf], vb);     mma16816(O[mf][2*dg],   ph[mf], vl);
                    mma16816(O[mf][2*dg],   pl[mf], vb);
                    mma16816(O[mf][2*dg+1], ph[mf], vb + 2); mma16816(O[mf][2*dg+1], ph[mf], vl + 2);
                    mma16816(O[mf][2*dg+1], pl[mf], vb + 2);
                }
            }
        }
        CP_WAIT0;
        __syncthreads();
    }

#pragma unroll
    for (int mf = 0; mf < 2; mf++)
#pragma unroll
        for (int rr = 0; rr < 2; rr++) {
            l_[mf][rr] += __shfl_xor_sync(0xffffffffu, l_[mf][rr], 1);
            l_[mf][rr] += __shfl_xor_sync(0xffffffffu, l_[mf][rr], 2);
        }
    const int b = bh / NH, h = bh - b * NH;
#pragma unroll
    for (int mf = 0; mf < 2; mf++) {
        const float inv0 = 1.f / l_[mf][0], inv1 = 1.f / l_[mf][1];
        const int r0 = q0 + qr + mf * 16 + (lane >> 2);
#pragma unroll
        for (int f = 0; f < 8; f++) {
            const int col = h * HD + f * 8 + (lane & 3) * 2;
            const size_t i0 = (size_t)(b * NTOK + r0) * CDIM + col;
            const size_t i1 = (size_t)(b * NTOK + r0 + 8) * CDIM + col;
            float x0 = O[mf][f][0] * inv0, x1 = O[mf][f][1] * inv0;
            float x2 = O[mf][f][2] * inv1, x3 = O[mf][f][3] * inv1;
            uint32_t h0 = pack_bf16(x0, x1), h1 = pack_bf16(x2, x3);
            *(uint32_t*)(g_AOhi + i0) = h0;
            *(uint32_t*)(g_AOlo + i0) = pack_bf16(x0 - lo_f(h0), x1 - hi_f(h0));
            *(uint32_t*)(g_AOhi + i1) = h1;
            *(uint32_t*)(g_AOlo + i1) = pack_bf16(x2 - lo_f(h1), x3 - hi_f(h1));
        }
    }
}

// ---------------------------------------------------------------------------
extern "C" void kernel_launch(void* const* d_in, const int* in_sizes, int n_in,
                              void* d_out, int out_size)
{
    (void)in_sizes; (void)n_in; (void)out_size;
    const float* x      = (const float*)d_in[0];
    const float* qkv_w  = (const float*)d_in[1];
    const float* qkv_b  = (const float*)d_in[2];
    const float* proj_w = (const float*)d_in[3];
    const float* proj_b = (const float*)d_in[4];
    const float* rph    = (const float*)d_in[5];
    const float* rpw    = (const float*)d_in[6];
    float* out = (float*)d_out;
    float* kv  = out + OUT_ELEMS;

    static void *pXhi, *pXlo, *pWqhi, *pWqlo, *pWphi, *pWplo, *pAOhi, *pAOlo;
    cudaGetSymbolAddress(&pXhi, g_Xhi);   cudaGetSymbolAddress(&pXlo, g_Xlo);
    cudaGetSymbolAddress(&pWqhi, g_Wqhi); cudaGetSymbolAddress(&pWqlo, g_Wqlo);
    cudaGetSymbolAddress(&pWphi, g_Wphi); cudaGetSymbolAddress(&pWplo, g_Wplo);
    cudaGetSymbolAddress(&pAOhi, g_AOhi); cudaGetSymbolAddress(&pAOlo, g_AOlo);

    cudaFuncSetAttribute(rel_mma, cudaFuncAttributeMaxDynamicSharedMemorySize, RSM_TOT);
    cudaFuncSetAttribute(attn_mma, cudaFuncAttributeMaxDynamicSharedMemorySize, ASM_TOT);

    cvt_all<<<CVT_NB1 + CVT_NB2 + CVT_NB3, 256>>>(x, qkv_w, proj_w);

    gemm_mma<<<dim3(18, 64), 256>>>(
        (const __nv_bfloat16*)pXhi, (const __nv_bfloat16*)pXlo,
        (const __nv_bfloat16*)pWqhi, (const __nv_bfloat16*)pWqlo,
        qkv_b, nullptr, kv, 1);

    rel_mma<<<dim3(96, 16), 128, RSM_TOT>>>(rph, rpw);

    attn_mma<<<dim3(8, 96), 128, ASM_TOT>>>();

    gemm_mma<<<dim3(6, 64), 256>>>(
        (const __nv_bfloat16*)pAOhi, (const __nv_bfloat16*)pAOlo,
        (const __nv_bfloat16*)pWphi, (const __nv_bfloat16*)pWplo,
        proj_b, out, nullptr, 0);
}

// round 16
// speedup vs baseline: 1.0634x; 1.0634x over previous
#include <cuda_runtime.h>
#include <cuda_bf16.h>
#include <cstdint>

#define NTOK 1024
#define CDIM 768
#define NH   12
#define HD   64
#define NB   8
#define BHN  (NB*NH)               /* 96  */
#define KV_ELEMS (BHN*NTOK*HD)     /* 6291456 */
#define OUT_ELEMS (NB*NTOK*CDIM)   /* 6291456 */

__device__ float g_REL[KV_ELEMS];   // per (bh,n): [0,32)=rel_h, [32,64)=rel_w (×log2e)

// bf16 hi/lo split buffers
__device__ __nv_bfloat16 g_Xhi[OUT_ELEMS],  g_Xlo[OUT_ELEMS];
__device__ __nv_bfloat16 g_Wqhi[3*CDIM*CDIM], g_Wqlo[3*CDIM*CDIM];
__device__ __nv_bfloat16 g_Wphi[CDIM*CDIM], g_Wplo[CDIM*CDIM];
__device__ __nv_bfloat16 g_AOhi[OUT_ELEMS], g_AOlo[OUT_ELEMS];
__device__ __nv_bfloat16 g_Qhi[KV_ELEMS], g_Qlo[KV_ELEMS];   // scaled by 0.125*log2e
__device__ __nv_bfloat16 g_Khi[KV_ELEMS], g_Klo[KV_ELEMS];
__device__ __nv_bfloat16 g_Vhi[KV_ELEMS], g_Vlo[KV_ELEMS];

// single dynamic smem symbol shared by all kernels
extern __shared__ __align__(16) char dyn_sm[];

// ---------------------------------------------------------------------------
__device__ __forceinline__ uint32_t smem_u32(const void* p) {
    uint32_t a;
    asm("{ .reg .u64 t; cvta.to.shared.u64 t, %1; cvt.u32.u64 %0, t; }" : "=r"(a) : "l"(p));
    return a;
}
__device__ __forceinline__ void ldm_x4(uint32_t* r, uint32_t addr) {
    asm volatile("ldmatrix.sync.aligned.m8n8.x4.shared.b16 {%0,%1,%2,%3}, [%4];"
                 : "=r"(r[0]), "=r"(r[1]), "=r"(r[2]), "=r"(r[3]) : "r"(addr));
}
__device__ __forceinline__ void ldm_x4t(uint32_t* r, uint32_t addr) {
    asm volatile("ldmatrix.sync.aligned.m8n8.x4.trans.shared.b16 {%0,%1,%2,%3}, [%4];"
                 : "=r"(r[0]), "=r"(r[1]), "=r"(r[2]), "=r"(r[3]) : "r"(addr));
}
__device__ __forceinline__ void mma16816(float* d, const uint32_t* a, const uint32_t* b) {
    asm volatile(
        "mma.sync.aligned.m16n8k16.row.col.f32.bf16.bf16.f32 "
        "{%0,%1,%2,%3}, {%4,%5,%6,%7}, {%8,%9}, {%0,%1,%2,%3};"
        : "+f"(d[0]), "+f"(d[1]), "+f"(d[2]), "+f"(d[3])
        : "r"(a[0]), "r"(a[1]), "r"(a[2]), "r"(a[3]), "r"(b[0]), "r"(b[1]));
}
__device__ __forceinline__ void sts128(uint32_t addr, uint4 v) {
    asm volatile("st.shared.v4.b32 [%0], {%1, %2, %3, %4};"
                 :: "r"(addr), "r"(v.x), "r"(v.y), "r"(v.z), "r"(v.w) : "memory");
}
__device__ __forceinline__ void cp16(uint32_t dst, const void* src) {
    asm volatile("cp.async.cg.shared.global [%0], [%1], 16;" :: "r"(dst), "l"(src));
}
#define CP_COMMIT asm volatile("cp.async.commit_group;" ::: "memory")
#define CP_WAIT0  asm volatile("cp.async.wait_group 0;" ::: "memory")

// 32B-row swizzle (gemm tiles)
__device__ __forceinline__ uint32_t tswz(int r, int c) {
    return (uint32_t)(r * 32 + 16 * (c ^ ((r >> 2) & 1)));
}
// 128B-row swizzle (attention tiles)
__device__ __forceinline__ uint32_t a128(int r, int c) {
    return (uint32_t)(r * 128 + 16 * (c ^ (r & 7)));
}
// pack (lo, hi) floats -> bf16x2
__device__ __forceinline__ uint32_t pack_bf16(float lo, float hi) {
    uint32_t r;
    asm("cvt.rn.bf16x2.f32 %0, %1, %2;" : "=r"(r) : "f"(hi), "f"(lo));
    return r;
}
__device__ __forceinline__ float lo_f(uint32_t h) { return __uint_as_float(h << 16); }
__device__ __forceinline__ float hi_f(uint32_t h) { return __uint_as_float(h & 0xFFFF0000u); }

// fast exp2 on the FMA pipe: input already in log2 domain.
__device__ __forceinline__ float fexp2(float y) {
    float r = y + 12582912.f;
    float n = r - 12582912.f;
    float f = y - n;
    uint32_t i = __float_as_uint(r);
    float s = __uint_as_float((i + (uint32_t)(127 - 0x4B400000)) << 23);
    float p = 0.00961812911f;
    p = fmaf(p, f, 0.0555041087f);
    p = fmaf(p, f, 0.240226507f);
    p = fmaf(p, f, 0.69314718056f);
    p = fmaf(p, f, 1.0f);
    return s * p;
}

// ---------------------------------------------------------------------------
// Fused conversion: one launch converts X, qkv_w, proj_w to bf16 hi/lo.
// ---------------------------------------------------------------------------
#define CVT_NB1 (OUT_ELEMS / 1024)
#define CVT_NB2 ((3 * CDIM * CDIM) / 1024)
#define CVT_NB3 ((CDIM * CDIM) / 1024)

__global__ void __launch_bounds__(256) cvt_all(
        const float* __restrict__ x, const float* __restrict__ qw,
        const float* __restrict__ pw)
{
    const float* src;
    __nv_bfloat16 *hi, *lo;
    int base;
    if (blockIdx.x < CVT_NB1) {
        src = x; hi = g_Xhi; lo = g_Xlo; base = blockIdx.x;
    } else if (blockIdx.x < CVT_NB1 + CVT_NB2) {
        src = qw; hi = g_Wqhi; lo = g_Wqlo; base = blockIdx.x - CVT_NB1;
    } else {
        src = pw; hi = g_Wphi; lo = g_Wplo; base = blockIdx.x - CVT_NB1 - CVT_NB2;
    }
    int i = (base * 256 + threadIdx.x) * 4;
    float4 v = *(const float4*)(src + i);
    uint32_t h0 = pack_bf16(v.x, v.y), h1 = pack_bf16(v.z, v.w);
    uint32_t l0 = pack_bf16(v.x - lo_f(h0), v.y - hi_f(h0));
    uint32_t l1 = pack_bf16(v.z - lo_f(h1), v.w - hi_f(h1));
    ((uint32_t*)(hi + i))[0] = h0; ((uint32_t*)(hi + i))[1] = h1;
    ((uint32_t*)(lo + i))[0] = l0; ((uint32_t*)(lo + i))[1] = l1;
}

// ---------------------------------------------------------------------------
// HMMA bf16x3 GEMM with cp.async 2-stage pipeline (proven config).
// ---------------------------------------------------------------------------
#define STG 16384

__global__ void __launch_bounds__(256, 2) gemm_mma(
        const __nv_bfloat16* __restrict__ Ahi, const __nv_bfloat16* __restrict__ Alo,
        const __nv_bfloat16* __restrict__ Bhi, const __nv_bfloat16* __restrict__ Blo,
        const float* __restrict__ bias, float* __restrict__ out0,
        float* __restrict__ out1, int mode)
{
    __shared__ __align__(16) char smem[2 * STG];
    const uint32_t sb = smem_u32(smem);
    const int tid = threadIdx.x, wid = tid >> 5, lane = tid & 31;
    const int m0 = blockIdx.y * 128, n0 = blockIdx.x * 128;
    const int wm = wid & 1, wn = wid >> 1;

    const int lr = tid >> 1, lc = tid & 1;
    const uint32_t soff = tswz(lr, lc);
    const __nv_bfloat16* gAh = Ahi + (size_t)(m0 + lr) * CDIM + lc * 8;
    const __nv_bfloat16* gAl = Alo + (size_t)(m0 + lr) * CDIM + lc * 8;
    const __nv_bfloat16* gBh = Bhi + (size_t)(n0 + lr) * CDIM + lc * 8;
    const __nv_bfloat16* gBl = Blo + (size_t)(n0 + lr) * CDIM + lc * 8;

    uint32_t aoff[4], boff[2];
#pragma unroll
    for (int mf = 0; mf < 4; mf++) {
        int r = wm * 64 + mf * 16 + (lane & 7) + ((lane >> 3) & 1) * 8;
        aoff[mf] = tswz(r, lane >> 4);
    }
#pragma unroll
    for (int g = 0; g < 2; g++) {
        int r = wn * 32 + g * 16 + ((lane >> 4) & 1) * 8 + (lane & 7);
        boff[g] = tswz(r, (lane >> 3) & 1);
    }

    float acc[4][4][4];
#pragma unroll
    for (int i = 0; i < 4; i++)
#pragma unroll
        for (int j = 0; j < 4; j++)
#pragma unroll
            for (int v = 0; v < 4; v++) acc[i][j][v] = 0.f;

    cp16(sb + soff, gAh);
    cp16(sb + 4096 + soff, gAl);
    cp16(sb + 8192 + soff, gBh);
    cp16(sb + 12288 + soff, gBl);
    CP_COMMIT; CP_WAIT0;
    __syncthreads();

    for (int kt = 0; kt < 48; kt++) {
        const uint32_t cur = sb + (kt & 1) * STG;
        if (kt < 47) {
            const uint32_t nxt = sb + ((kt + 1) & 1) * STG;
            const int ko = (kt + 1) * 16;
            cp16(nxt + soff, gAh + ko);
            cp16(nxt + 4096 + soff, gAl + ko);
            cp16(nxt + 8192 + soff, gBh + ko);
            cp16(nxt + 12288 + soff, gBl + ko);
            CP_COMMIT;
        }

        uint32_t bh[8], bl[8];
        ldm_x4(bh,     cur + 8192  + boff[0]);
        ldm_x4(bh + 4, cur + 8192  + boff[1]);
        ldm_x4(bl,     cur + 12288 + boff[0]);
        ldm_x4(bl + 4, cur + 12288 + boff[1]);

#pragma unroll
        for (int mf = 0; mf < 4; mf++) {
            uint32_t ah[4], al[4];
            ldm_x4(ah, cur + aoff[mf]);
            ldm_x4(al, cur + 4096 + aoff[mf]);
#pragma unroll
            for (int nf = 0; nf < 4; nf++) {
                const uint32_t* ph = &bh[(nf >> 1) * 4 + (nf & 1) * 2];
                const uint32_t* pl = &bl[(nf >> 1) * 4 + (nf & 1) * 2];
                mma16816(acc[mf][nf], ah, ph);
                mma16816(acc[mf][nf], ah, pl);
                mma16816(acc[mf][nf], al, ph);
            }
        }
        CP_WAIT0;
        __syncthreads();
    }

#pragma unroll
    for (int mf = 0; mf < 4; mf++) {
#pragma unroll
        for (int nf = 0; nf < 4; nf++) {
            const int col = n0 + wn * 32 + nf * 8 + (lane & 3) * 2;
            const int r1 = m0 + wm * 64 + mf * 16 + (lane >> 2);
            const float2 bb = *(const float2*)(bias + col);
            float2 v0 = make_float2(acc[mf][nf][0] + bb.x, acc[mf][nf][1] + bb.y);
            float2 v1 = make_float2(acc[mf][nf][2] + bb.x, acc[mf][nf][3] + bb.y);
            if (mode == 0) {
                *(float2*)(out0 + (size_t)r1 * CDIM + col) = v0;
                *(float2*)(out0 + (size_t)(r1 + 8) * CDIM + col) = v1;
            } else {
                const int t = col / CDIM, rem = col - t * CDIM;
                const int h = rem >> 6, d = rem & 63;
                float* dst = (t == 1) ? out1 : out1 + KV_ELEMS;
                __nv_bfloat16* hib = (t == 0) ? g_Qhi : (t == 1) ? g_Khi : g_Vhi;
                __nv_bfloat16* lob = (t == 0) ? g_Qlo : (t == 1) ? g_Klo : g_Vlo;
                // Q scale = 0.125 * log2(e): scores and rel bias land in log2 domain
                const float sc = (t == 0) ? 0.18033688011112042f : 1.f;
#pragma unroll
                for (int rr = 0; rr < 2; rr++) {
                    const int row = r1 + rr * 8;
                    const int b = row >> 10, n = row & (NTOK - 1);
                    const size_t idx = ((size_t)(b * NH + h) << 16) | ((size_t)n << 6) | (size_t)d;
                    float2 vv = rr ? v1 : v0;
                    if (t != 0) *(float2*)(dst + idx) = vv;
                    float sx = vv.x * sc, sy = vv.y * sc;
                    uint32_t hh = pack_bf16(sx, sy);
                    uint32_t ll = pack_bf16(sx - lo_f(hh), sy - hi_f(hh));
                    *(uint32_t*)(hib + idx) = hh;
                    *(uint32_t*)(lob + idx) = ll;
                }
            }
        }
    }
}

// ---------------------------------------------------------------------------
// rel-pos projections via HMMA (bf16x3). (R10 proven config.)
// ---------------------------------------------------------------------------
#define RSM_TOT 49152

__global__ void __launch_bounds__(128) rel_mma(
        const float* __restrict__ rph, const float* __restrict__ rpw)
{
    const uint32_t sb = smem_u32(dyn_sm);
    const uint32_t Qh = sb, Ql = sb + 16384;
    const uint32_t Th = sb + 32768, Tl = sb + 40960;

    const int bh = blockIdx.x;
    const int grp = blockIdx.y;
    const bool isw = grp >= 8;
    const int g = grp & 7;
    const int tid = threadIdx.x, wid = tid >> 5, lane = tid & 31;

    {
        const int s = tid;
        const int q = isw ? (g * 4 + (s >> 5) + 32 * (s & 31))
                          : (g * 128 + s);
        const size_t gb = ((size_t)bh << 16) | ((size_t)q << 6);
        const uint4* qh = (const uint4*)(g_Qhi + gb);
        const uint4* ql = (const uint4*)(g_Qlo + gb);
#pragma unroll
        for (int c = 0; c < 8; c++) {
            sts128(Qh + a128(s, c), qh[c]);
            sts128(Ql + a128(s, c), ql[c]);
        }
    }
    {
        const float* tab = isw ? rpw : rph;
        for (int i = tid; i < 63 * 32; i += 128) {
            const int r = i >> 5, c2 = (i & 31) * 2;
            float2 v = *(const float2*)(tab + r * 64 + c2);
            uint32_t h = pack_bf16(v.x, v.y);
            uint32_t l = pack_bf16(v.x - lo_f(h), v.y - hi_f(h));
            const int boffb = c2 * 2;
            const uint32_t a = a128(r, boffb >> 4) + (boffb & 15);
            *(uint32_t*)(dyn_sm + (Th - sb) + a) = h;
            *(uint32_t*)(dyn_sm + (Tl - sb) + a) = l;
        }
    }
    __syncthreads();

    const int vv = g * 4 + wid;
    const int abase = wid * 32;

    float acc[2][4][4];
#pragma unroll
    for (int mf = 0; mf < 2; mf++)
#pragma unroll
        for (int nf = 0; nf < 4; nf++)
#pragma unroll
            for (int v = 0; v < 4; v++) acc[mf][nf][v] = 0.f;

    const int arow_l = (lane & 7) + ((lane >> 3) & 1) * 8;
    const int nloc  = ((lane >> 4) & 1) * 8 + (lane & 7);
    const int bchunk = (lane >> 3) & 1;

#pragma unroll
    for (int ks = 0; ks < 4; ks++) {
        uint32_t ah[2][4], al[2][4];
#pragma unroll
        for (int mf = 0; mf < 2; mf++) {
            const uint32_t aaddr = Qh + a128(abase + mf * 16 + arow_l, 2 * ks + (lane >> 4));
            ldm_x4(ah[mf], aaddr);
            ldm_x4(al[mf], aaddr + 16384);
        }
#pragma unroll
        for (int g2 = 0; g2 < 2; g2++) {
            const int trow = vv + 31 - (g2 * 16 + nloc);
            uint32_t bhf[4], blf[4];
            const uint32_t baddr = a128(trow, 2 * ks + bchunk);
            ldm_x4(bhf, Th + baddr);
            ldm_x4(blf, Tl + baddr);
#pragma unroll
            for (int mf = 0; mf < 2; mf++) {
#pragma unroll
                for (int half = 0; half < 2; half++) {
                    float* d = acc[mf][g2 * 2 + half];
                    mma16816(d, ah[mf], bhf + half * 2);
                    mma16816(d, ah[mf], blf + half * 2);
                    mma16816(d, al[mf], bhf + half * 2);
                }
            }
        }
    }

    const int cbase = isw ? 32 : 0;
#pragma unroll
    for (int mf = 0; mf < 2; mf++)
#pragma unroll
        for (int nf = 0; nf < 4; nf++) {
            const int col = cbase + nf * 8 + (lane & 3) * 2;
#pragma unroll
            for (int rr = 0; rr < 2; rr++) {
                const int rl = mf * 16 + (lane >> 2) + rr * 8;
                const int q = isw ? (vv + 32 * rl) : (g * 128 + abase + rl);
                float2 o = make_float2(acc[mf][nf][rr * 2] * 8.f,
                                       acc[mf][nf][rr * 2 + 1] * 8.f);
                *(float2*)(g_REL + (((size_t)bh << 16) | ((size_t)q << 6)) + col) = o;
            }
        }
}

// ---------------------------------------------------------------------------
// Tensor-core flash attention: 4 warps x 32 q-rows, bf16x3, base-2 fixed-
// shift softmax, cp.async double-buffered K/V. (R14 proven config.)
// ---------------------------------------------------------------------------
#define ASM_TOT 114688
#define KVB 49152

__global__ void __launch_bounds__(128, 2) attn_mma()
{
    const uint32_t sb = smem_u32(dyn_sm);
    const uint32_t Qh = sb, Ql = sb + 16384;
    float* RELh = (float*)(dyn_sm + 32768);

    const int bh = blockIdx.y, q0 = blockIdx.x * 128;
    const int tid = threadIdx.x, wid = tid >> 5, lane = tid & 31;

    const int arr = wid, kr0 = lane;
    const __nv_bfloat16* kvsrc = (arr == 0) ? g_Khi : (arr == 1) ? g_Klo
                               : (arr == 2) ? g_Vhi : g_Vlo;
    kvsrc += ((size_t)bh << 16) | ((size_t)kr0 << 6);

    {
        const uint32_t dst = sb + KVB + arr * 8192;
#pragma unroll
        for (int c = 0; c < 8; c++) {
            cp16(dst + a128(kr0, c), kvsrc + c * 8);
            cp16(dst + a128(kr0 + 32, c), kvsrc + 32 * 64 + c * 8);
        }
        CP_COMMIT;
    }

    {
        const int row = tid;
        const size_t gb = ((size_t)bh << 16) | ((size_t)(q0 + row) << 6);
        const uint4* qh = (const uint4*)(g_Qhi + gb);
        const uint4* ql = (const uint4*)(g_Qlo + gb);
#pragma unroll
        for (int c = 0; c < 8; c++) {
            sts128(Qh + a128(row, c), qh[c]);
            sts128(Ql + a128(row, c), ql[c]);
        }
        const float4* rs = (const float4*)(g_REL + gb);
        float4* rd = (float4*)(RELh + row * 32);
#pragma unroll
        for (int c = 0; c < 8; c++) rd[c] = rs[c];
    }

    const int qr = wid * 32;

    float rw[4][8];
#pragma unroll
    for (int mf = 0; mf < 2; mf++)
#pragma unroll
        for (int rr = 0; rr < 2; rr++) {
            const int row = q0 + qr + mf * 16 + (lane >> 2) + rr * 8;
            const float* src = g_REL + (((size_t)bh << 16) | ((size_t)row << 6)) + 32;
#pragma unroll
            for (int c = 0; c < 2; c++)
#pragma unroll
                for (int f4 = 0; f4 < 4; f4++)
                    rw[mf * 2 + rr][c + 2 * f4] = src[(lane & 3) * 2 + c + f4 * 8];
        }

    float O[2][8][4];
#pragma unroll
    for (int mf = 0; mf < 2; mf++)
#pragma unroll
        for (int f = 0; f < 8; f++)
#pragma unroll
            for (int v = 0; v < 4; v++) O[mf][f][v] = 0.f;
    float l_[2][2] = {{0.f, 0.f}, {0.f, 0.f}};

    CP_WAIT0;
    __syncthreads();

    for (int t = 0; t < 16; t++) {
        const uint32_t kvb = sb + KVB + (t & 1) * 32768;
        if (t < 15) {
            const uint32_t dst = sb + KVB + ((t + 1) & 1) * 32768 + arr * 8192;
            const __nv_bfloat16* src = kvsrc + ((size_t)(t + 1) << 12);
#pragma unroll
            for (int c = 0; c < 8; c++) {
                cp16(dst + a128(kr0, c), src + c * 8);
                cp16(dst + a128(kr0 + 32, c), src + 32 * 64 + c * 8);
            }
            CP_COMMIT;
        }
        const uint32_t Kh = kvb, Vh = kvb + 16384;

        float S[2][8][4];
#pragma unroll
        for (int mf = 0; mf < 2; mf++)
#pragma unroll
            for (int f = 0; f < 8; f++)
#pragma unroll
                for (int v = 0; v < 4; v++) S[mf][f][v] = 0.f;

#pragma unroll
        for (int ks = 0; ks < 4; ks++) {
            uint32_t ah[2][4], al[2][4];
#pragma unroll
            for (int mf = 0; mf < 2; mf++) {
                const uint32_t aaddr = Qh + a128(qr + mf * 16 + (lane & 7) + ((lane >> 3) & 1) * 8,
                                                 2 * ks + (lane >> 4));
                ldm_x4(ah[mf], aaddr);
                ldm_x4(al[mf], aaddr + 16384);
            }
#pragma unroll
            for (int g = 0; g < 4; g++) {
                uint32_t kb[4], kl[4];
                const uint32_t kaddr = Kh + a128(g * 16 + ((lane >> 4) & 1) * 8 + (lane & 7),
                                                 2 * ks + ((lane >> 3) & 1));
                ldm_x4(kb, kaddr);
                ldm_x4(kl, kaddr + 8192);
#pragma unroll
                for (int mf = 0; mf < 2; mf++) {
                    mma16816(S[mf][2*g],   ah[mf], kb);     mma16816(S[mf][2*g],   ah[mf], kl);
                    mma16816(S[mf][2*g],   al[mf], kb);
                    mma16816(S[mf][2*g+1], ah[mf], kb + 2); mma16816(S[mf][2*g+1], ah[mf], kl + 2);
                    mma16816(S[mf][2*g+1], al[mf], kb + 2);
                }
            }
        }

        const int khb = t * 2;
#pragma unroll
        for (int mf = 0; mf < 2; mf++)
#pragma unroll
            for (int rr = 0; rr < 2; rr++) {
                const int row = qr + mf * 16 + (lane >> 2) + rr * 8;
                const float rh0 = RELh[row * 32 + khb], rh1 = RELh[row * 32 + khb + 1];
                float ps = 0.f;
#pragma unroll
                for (int f = 0; f < 8; f++) {
                    const float rh = (f < 4) ? rh0 : rh1;
                    float p0 = fexp2(S[mf][f][rr*2]   + rh + rw[mf*2+rr][0 + 2*(f & 3)]);
                    float p1 = fexp2(S[mf][f][rr*2+1] + rh + rw[mf*2+rr][1 + 2*(f & 3)]);
                    S[mf][f][rr*2] = p0; S[mf][f][rr*2+1] = p1;
                    ps += p0 + p1;
                }
                l_[mf][rr] += ps;
            }

        // P repack (hi/lo) + PV MMAs (full bf16x3)
#pragma unroll
        for (int ks = 0; ks < 4; ks++) {
            uint32_t ph[2][4], pl[2][4];
#pragma unroll
            for (int mf = 0; mf < 2; mf++)
#pragma unroll
                for (int part = 0; part < 4; part++) {
                    const int f = 2 * ks + (part >> 1);
                    const float x0 = S[mf][f][(part & 1) * 2], x1 = S[mf][f][(part & 1) * 2 + 1];
                    uint32_t h = pack_bf16(x0, x1);
                    ph[mf][part] = h;
                    pl[mf][part] = pack_bf16(x0 - lo_f(h), x1 - hi_f(h));
                }
#pragma unroll
            for (int dg = 0; dg < 4; dg++) {
                uint32_t vb[4], vl[4];
                const uint32_t vaddr = Vh + a128(ks * 16 + ((lane >> 3) & 1) * 8 + (lane & 7),
                                                 2 * dg + (lane >> 4));
                ldm_x4t(vb, vaddr);
                ldm_x4t(vl, vaddr + 8192);
#pragma unroll
                for (int mf = 0; mf < 2; mf++) {
                    mma16816(O[mf][2*dg],   ph[mf], vb);     mma16816(O[mf][2*dg],   ph[mf], vl);
                    mma16816(O[mf][2*dg],   pl[mf], vb);
                    mma16816(O[mf][2*dg+1], ph[mf], vb + 2); mma16816(O[mf][2*dg+1], ph[mf], vl + 2);
                    mma16816(O[mf][2*dg+1], pl[mf], vb + 2);
                }
            }
        }
        CP_WAIT0;
        __syncthreads();
    }

#pragma unroll
    for (int mf = 0; mf < 2; mf++)
#pragma unroll
        for (int rr = 0; rr < 2; rr++) {
            l_[mf][rr] += __shfl_xor_sync(0xffffffffu, l_[mf][rr], 1);
            l_[mf][rr] += __shfl_xor_sync(0xffffffffu, l_[mf][rr], 2);
        }
    const int b = bh / NH, h = bh - b * NH;
#pragma unroll
    for (int mf = 0; mf < 2; mf++) {
        const float inv0 = 1.f / l_[mf][0], inv1 = 1.f / l_[mf][1];
        const int r0 = q0 + qr + mf * 16 + (lane >> 2);
#pragma unroll
        for (int f = 0; f < 8; f++) {
            const int col = h * HD + f * 8 + (lane & 3) * 2;
            const size_t i0 = (size_t)(b * NTOK + r0) * CDIM + col;
            const size_t i1 = (size_t)(b * NTOK + r0 + 8) * CDIM + col;
            float x0 = O[mf][f][0] * inv0, x1 = O[mf][f][1] * inv0;
            float x2 = O[mf][f][2] * inv1, x3 = O[mf][f][3] * inv1;
            uint32_t h0 = pack_bf16(x0, x1), h1 = pack_bf16(x2, x3);
            *(uint32_t*)(g_AOhi + i0) = h0;
            *(uint32_t*)(g_AOlo + i0) = pack_bf16(x0 - lo_f(h0), x1 - hi_f(h0));
            *(uint32_t*)(g_AOhi + i1) = h1;
            *(uint32_t*)(g_AOlo + i1) = pack_bf16(x2 - lo_f(h1), x3 - hi_f(h1));
        }
    }
}

// ---------------------------------------------------------------------------
extern "C" void kernel_launch(void* const* d_in, const int* in_sizes, int n_in,
                              void* d_out, int out_size)
{
    (void)in_sizes; (void)n_in; (void)out_size;
    const float* x      = (const float*)d_in[0];
    const float* qkv_w  = (const float*)d_in[1];
    const float* qkv_b  = (const float*)d_in[2];
    const float* proj_w = (const float*)d_in[3];
    const float* proj_b = (const float*)d_in[4];
    const float* rph    = (const float*)d_in[5];
    const float* rpw    = (const float*)d_in[6];
    float* out = (float*)d_out;
    float* kv  = out + OUT_ELEMS;

    static void *pXhi, *pXlo, *pWqhi, *pWqlo, *pWphi, *pWplo, *pAOhi, *pAOlo;
    cudaGetSymbolAddress(&pXhi, g_Xhi);   cudaGetSymbolAddress(&pXlo, g_Xlo);
    cudaGetSymbolAddress(&pWqhi, g_Wqhi); cudaGetSymbolAddress(&pWqlo, g_Wqlo);
    cudaGetSymbolAddress(&pWphi, g_Wphi); cudaGetSymbolAddress(&pWplo, g_Wplo);
    cudaGetSymbolAddress(&pAOhi, g_AOhi); cudaGetSymbolAddress(&pAOlo, g_AOlo);

    cudaFuncSetAttribute(rel_mma, cudaFuncAttributeMaxDynamicSharedMemorySize, RSM_TOT);
    cudaFuncSetAttribute(attn_mma, cudaFuncAttributeMaxDynamicSharedMemorySize, ASM_TOT);

    cvt_all<<<CVT_NB1 + CVT_NB2 + CVT_NB3, 256>>>(x, qkv_w, proj_w);

    gemm_mma<<<dim3(18, 64), 256>>>(
        (const __nv_bfloat16*)pXhi, (const __nv_bfloat16*)pXlo,
        (const __nv_bfloat16*)pWqhi, (const __nv_bfloat16*)pWqlo,
        qkv_b, nullptr, kv, 1);

    rel_mma<<<dim3(96, 16), 128, RSM_TOT>>>(rph, rpw);

    attn_mma<<<dim3(8, 96), 128, ASM_TOT>>>();

    gemm_mma<<<dim3(6, 64), 256>>>(
        (const __nv_bfloat16*)pAOhi, (const __nv_bfloat16*)pAOlo,
        (const __nv_bfloat16*)pWphi, (const __nv_bfloat16*)pWplo,
        proj_b, out, nullptr, 0);
}